// round 3
// baseline (speedup 1.0000x reference)
#include <cuda_runtime.h>
#include <math.h>

#define N   8192
#define NZ  256
#define NC  128
#define DT_ 0.1f
#define SPLITS 4
#define CHUNK  (N / SPLITS)       // 2048 columns per split
#define CHUNK4 (CHUNK / 4)        // 512 float4 per split

// Scratch (allocation-guard-safe __device__ globals)
__device__ float g_r[N];                    // r = tanh(x+b)
__device__ float g_zpart[SPLITS][NZ];       // split-K partials of z = W_rz @ r
__device__ float g_rn[N];                   // r_new
__device__ float g_tpart[SPLITS][NZ + NC];  // split-K partials of z_new / c_new

__inline__ __device__ float dot4(float4 a, float4 b) {
    return a.x * b.x + a.y * b.y + a.z * b.z + a.w * b.w;
}

__inline__ __device__ float block_reduce(float v) {
    __shared__ float sm[8];
    const int lane = threadIdx.x & 31;
    const int wid  = threadIdx.x >> 5;
    #pragma unroll
    for (int o = 16; o; o >>= 1) v += __shfl_down_sync(0xffffffffu, v, o);
    if (lane == 0) sm[wid] = v;
    __syncthreads();
    if (wid == 0) {
        v = (lane < 8) ? sm[lane] : 0.f;
        #pragma unroll
        for (int o = 4; o; o >>= 1) v += __shfl_down_sync(0xffffffffu, v, o);
    }
    return v;  // valid in thread 0
}

// Kernel 1 (fused): computes r = tanh(x+b) for its column chunk (row==0 blocks
// persist it to g_r) and the split-K partial of z = W_rz @ r.
// Grid: NZ * SPLITS blocks, 256 threads. Each thread owns 8 contiguous columns.
__global__ void __launch_bounds__(256) k_rz(
    const float* __restrict__ x, const float* __restrict__ b,
    const float* __restrict__ W_rz)
{
    const int s   = blockIdx.x & (SPLITS - 1);
    const int row = blockIdx.x >> 2;
    const int c4  = s * CHUNK4 + threadIdx.x * 2;   // float4 index

    const float4* __restrict__ xv = (const float4*)x;
    const float4* __restrict__ bv = (const float4*)b;
    float4 x0 = xv[c4], x1 = xv[c4 + 1];
    float4 b0 = bv[c4], b1 = bv[c4 + 1];
    float4 r0, r1;
    r0.x = tanhf(x0.x + b0.x); r0.y = tanhf(x0.y + b0.y);
    r0.z = tanhf(x0.z + b0.z); r0.w = tanhf(x0.w + b0.w);
    r1.x = tanhf(x1.x + b1.x); r1.y = tanhf(x1.y + b1.y);
    r1.z = tanhf(x1.z + b1.z); r1.w = tanhf(x1.w + b1.w);

    if (row == 0) {
        ((float4*)g_r)[c4]     = r0;
        ((float4*)g_r)[c4 + 1] = r1;
    }

    const float4* __restrict__ w = (const float4*)(W_rz + (size_t)row * N);
    float acc = dot4(__ldcs(&w[c4]), r0) + dot4(__ldcs(&w[c4 + 1]), r1);
    acc = block_reduce(acc);
    if (threadIdx.x == 0) g_zpart[s][row] = acc;
}

// Kernel 2: big fused row update (one block per row, 256 threads).
// acc = W_rr[row,:]·r + W_epsr[row,:]·eps + W_zr[row,:]·z + W_cr[row,:]·c
// x_new = x + DT*(acc - x); r_new = tanh(x_new + b)
__global__ void __launch_bounds__(256) k_big(
    const float* __restrict__ W_rr, const float* __restrict__ W_zr,
    const float* __restrict__ W_cr, const float* __restrict__ W_epsr,
    const float* __restrict__ x,    const float* __restrict__ eps,
    const float* __restrict__ c,    const float* __restrict__ b,
    float* __restrict__ out)
{
    const int row = blockIdx.x;
    const int t   = threadIdx.x;

    const float4* __restrict__ w = (const float4*)(W_rr + (size_t)row * N);
    const float4* __restrict__ v = (const float4*)g_r;
    float a0 = 0.f, a1 = 0.f, a2 = 0.f, a3 = 0.f;
    #pragma unroll
    for (int i = 0; i < 8; i++) {
        const int k = t + i * 256;
        float4 a  = __ldcs(&w[k]);
        float4 rv = v[k];
        float d = dot4(a, rv);
        if ((i & 3) == 0) a0 += d;
        else if ((i & 3) == 1) a1 += d;
        else if ((i & 3) == 2) a2 += d;
        else a3 += d;
    }
    float acc = (a0 + a1) + (a2 + a3);

    // Side dots split across disjoint thread ranges (640 elems total)
    if (t < 64) {                               // W_epsr row: 256 f = 64 float4
        float4 a = __ldcs(((const float4*)(W_epsr + (size_t)row * NZ)) + t);
        float4 e = ((const float4*)eps)[t];
        acc += dot4(a, e);
    } else if (t < 128) {                       // W_zr row · z (sum of split partials)
        const int k = t - 64;
        float4 a  = __ldcs(((const float4*)(W_zr + (size_t)row * NZ)) + k);
        float4 q0 = ((const float4*)g_zpart[0])[k];
        float4 q1 = ((const float4*)g_zpart[1])[k];
        float4 q2 = ((const float4*)g_zpart[2])[k];
        float4 q3 = ((const float4*)g_zpart[3])[k];
        float4 zz = make_float4(q0.x + q1.x + q2.x + q3.x,
                                q0.y + q1.y + q2.y + q3.y,
                                q0.z + q1.z + q2.z + q3.z,
                                q0.w + q1.w + q2.w + q3.w);
        acc += dot4(a, zz);
    } else if (t < 160) {                       // W_cr row: 128 f = 32 float4
        const int k = t - 128;
        float4 a  = __ldcs(((const float4*)(W_cr + (size_t)row * NC)) + k);
        float4 cc = ((const float4*)c)[k];
        acc += dot4(a, cc);
    }

    acc = block_reduce(acc);
    if (t == 0) {
        float xv = x[row];
        float xn = xv + DT_ * (acc - xv);
        out[row] = xn;
        float rn = tanhf(xn + b[row]);
        out[N + row] = rn;
        g_rn[row] = rn;
    }
}

// Kernel 3: split-K partials for z_new (rows 0..255 of W_rz) and
// c_new (rows 0..127 of W_rc), all against r_new.
// Grid: (NZ+NC) * SPLITS blocks, 256 threads.
__global__ void __launch_bounds__(256) k_tail(
    const float* __restrict__ W_rz, const float* __restrict__ W_rc)
{
    const int s   = blockIdx.x & (SPLITS - 1);
    const int idx = blockIdx.x >> 2;
    const float* __restrict__ Wrow = (idx < NZ)
        ? (W_rz + (size_t)idx * N)
        : (W_rc + (size_t)(idx - NZ) * N);
    const float4* __restrict__ w = (const float4*)Wrow;
    const float4* __restrict__ v = (const float4*)g_rn;
    const int c4 = s * CHUNK4 + threadIdx.x * 2;

    float acc = dot4(__ldcs(&w[c4]), v[c4]) + dot4(__ldcs(&w[c4 + 1]), v[c4 + 1]);
    acc = block_reduce(acc);
    if (threadIdx.x == 0) g_tpart[s][idx] = acc;
}

// Kernel 4: finalize — sum split partials, write z_new, c_new, eps_new.
// EXACTLY NZ+NC = 384 threads; t < NZ also writes eps_new.
__global__ void k_fin(const float* __restrict__ z_tilde, float* __restrict__ out) {
    const int t = threadIdx.x;  // 0..383
    float v = g_tpart[0][t] + g_tpart[1][t] + g_tpart[2][t] + g_tpart[3][t];
    if (t < NZ) {
        out[2 * N + t] = v;                            // z_new
        out[2 * N + NZ + NC + t] = v - z_tilde[t];     // eps_new
    } else {
        out[2 * N + NZ + (t - NZ)] = v;                // c_new
    }
}

extern "C" void kernel_launch(void* const* d_in, const int* in_sizes, int n_in,
                              void* d_out, int out_size) {
    // metadata order: x, eps, c, z_tilde, W_rr, W_zr, W_cr, W_epsr, W_rz, W_rc, b
    const float* x       = (const float*)d_in[0];
    const float* eps     = (const float*)d_in[1];
    const float* c       = (const float*)d_in[2];
    const float* z_tilde = (const float*)d_in[3];
    const float* W_rr    = (const float*)d_in[4];
    const float* W_zr    = (const float*)d_in[5];
    const float* W_cr    = (const float*)d_in[6];
    const float* W_epsr  = (const float*)d_in[7];
    const float* W_rz    = (const float*)d_in[8];
    const float* W_rc    = (const float*)d_in[9];
    const float* b       = (const float*)d_in[10];
    float* out = (float*)d_out;

    k_rz  <<<NZ * SPLITS, 256>>>(x, b, W_rz);
    k_big <<<N, 256>>>(W_rr, W_zr, W_cr, W_epsr, x, eps, c, b, out);
    k_tail<<<(NZ + NC) * SPLITS, 256>>>(W_rz, W_rc);
    k_fin <<<1, NZ + NC>>>(z_tilde, out);
}

// round 4
// speedup vs baseline: 1.0109x; 1.0109x over previous
#include <cuda_runtime.h>
#include <math.h>

#define N   8192
#define NZ  256
#define NC  128
#define DT_ 0.1f
#define SPLITS 4
#define CHUNK  (N / SPLITS)       // 2048 columns per split
#define CHUNK4 (CHUNK / 4)        // 512 float4 per split
#define ROWS_Z 4                  // rows per k_rz block

// Scratch (allocation-guard-safe __device__ globals; zero-initialized at load)
__device__ float g_r[N];                    // r = tanh(x+b)
__device__ float g_zpart[SPLITS][NZ];       // split-K partials of z = W_rz @ r
__device__ float g_rn[N];                   // r_new
__device__ float g_tpart[SPLITS][NZ + NC];  // split-K partials of z_new / c_new
__device__ int   g_cnt[NZ + NC];            // per-row split completion counters

__inline__ __device__ float dot4(float4 a, float4 b) {
    return a.x * b.x + a.y * b.y + a.z * b.z + a.w * b.w;
}

__inline__ __device__ float block_reduce(float v) {
    __shared__ float sm[8];
    const int lane = threadIdx.x & 31;
    const int wid  = threadIdx.x >> 5;
    #pragma unroll
    for (int o = 16; o; o >>= 1) v += __shfl_down_sync(0xffffffffu, v, o);
    if (lane == 0) sm[wid] = v;
    __syncthreads();
    if (wid == 0) {
        v = (lane < 8) ? sm[lane] : 0.f;
        #pragma unroll
        for (int o = 4; o; o >>= 1) v += __shfl_down_sync(0xffffffffu, v, o);
    }
    return v;  // valid in thread 0
}

// Reduce 4 values at once (one barrier pass). Valid in thread 0.
__inline__ __device__ float4 block_reduce4(float4 v) {
    __shared__ float4 sm4[8];
    const int lane = threadIdx.x & 31;
    const int wid  = threadIdx.x >> 5;
    #pragma unroll
    for (int o = 16; o; o >>= 1) {
        v.x += __shfl_down_sync(0xffffffffu, v.x, o);
        v.y += __shfl_down_sync(0xffffffffu, v.y, o);
        v.z += __shfl_down_sync(0xffffffffu, v.z, o);
        v.w += __shfl_down_sync(0xffffffffu, v.w, o);
    }
    if (lane == 0) sm4[wid] = v;
    __syncthreads();
    if (wid == 0) {
        v = (lane < 8) ? sm4[lane] : make_float4(0.f, 0.f, 0.f, 0.f);
        #pragma unroll
        for (int o = 4; o; o >>= 1) {
            v.x += __shfl_down_sync(0xffffffffu, v.x, o);
            v.y += __shfl_down_sync(0xffffffffu, v.y, o);
            v.z += __shfl_down_sync(0xffffffffu, v.z, o);
            v.w += __shfl_down_sync(0xffffffffu, v.w, o);
        }
    }
    return v;
}

// Kernel 1 (fused): each block computes tanh(x+b) for its column chunk ONCE
// (row-group 0 persists it to g_r) and split-K partials of z = W_rz @ r for
// ROWS_Z=4 rows. Grid: (NZ/ROWS_Z) * SPLITS = 256 blocks, 256 threads.
__global__ void __launch_bounds__(256) k_rz(
    const float* __restrict__ x, const float* __restrict__ b,
    const float* __restrict__ W_rz)
{
    const int s    = blockIdx.x & (SPLITS - 1);
    const int rg   = blockIdx.x >> 2;          // row group
    const int row0 = rg * ROWS_Z;
    const int c4   = s * CHUNK4 + threadIdx.x * 2;   // float4 index

    const float4* __restrict__ xv = (const float4*)x;
    const float4* __restrict__ bv = (const float4*)b;
    float4 x0 = xv[c4], x1 = xv[c4 + 1];
    float4 b0 = bv[c4], b1 = bv[c4 + 1];
    float4 r0, r1;
    r0.x = tanhf(x0.x + b0.x); r0.y = tanhf(x0.y + b0.y);
    r0.z = tanhf(x0.z + b0.z); r0.w = tanhf(x0.w + b0.w);
    r1.x = tanhf(x1.x + b1.x); r1.y = tanhf(x1.y + b1.y);
    r1.z = tanhf(x1.z + b1.z); r1.w = tanhf(x1.w + b1.w);

    if (rg == 0) {
        ((float4*)g_r)[c4]     = r0;
        ((float4*)g_r)[c4 + 1] = r1;
    }

    float4 acc;
    {
        const float4* w0 = (const float4*)(W_rz + (size_t)(row0 + 0) * N);
        const float4* w1 = (const float4*)(W_rz + (size_t)(row0 + 1) * N);
        const float4* w2 = (const float4*)(W_rz + (size_t)(row0 + 2) * N);
        const float4* w3 = (const float4*)(W_rz + (size_t)(row0 + 3) * N);
        acc.x = dot4(__ldcs(&w0[c4]), r0) + dot4(__ldcs(&w0[c4 + 1]), r1);
        acc.y = dot4(__ldcs(&w1[c4]), r0) + dot4(__ldcs(&w1[c4 + 1]), r1);
        acc.z = dot4(__ldcs(&w2[c4]), r0) + dot4(__ldcs(&w2[c4 + 1]), r1);
        acc.w = dot4(__ldcs(&w3[c4]), r0) + dot4(__ldcs(&w3[c4 + 1]), r1);
    }
    acc = block_reduce4(acc);
    if (threadIdx.x == 0) {
        g_zpart[s][row0 + 0] = acc.x;
        g_zpart[s][row0 + 1] = acc.y;
        g_zpart[s][row0 + 2] = acc.z;
        g_zpart[s][row0 + 3] = acc.w;
    }
}

// Kernel 2: big fused row update (one block per row, 256 threads).
// acc = W_rr[row,:]·r + W_epsr[row,:]·eps + W_zr[row,:]·z + W_cr[row,:]·c
// x_new = x + DT*(acc - x); r_new = tanh(x_new + b)
__global__ void __launch_bounds__(256) k_big(
    const float* __restrict__ W_rr, const float* __restrict__ W_zr,
    const float* __restrict__ W_cr, const float* __restrict__ W_epsr,
    const float* __restrict__ x,    const float* __restrict__ eps,
    const float* __restrict__ c,    const float* __restrict__ b,
    float* __restrict__ out)
{
    const int row = blockIdx.x;
    const int t   = threadIdx.x;

    const float4* __restrict__ w = (const float4*)(W_rr + (size_t)row * N);
    const float4* __restrict__ v = (const float4*)g_r;
    float a0 = 0.f, a1 = 0.f, a2 = 0.f, a3 = 0.f;
    #pragma unroll
    for (int i = 0; i < 8; i++) {
        const int k = t + i * 256;
        float4 a  = __ldcs(&w[k]);
        float4 rv = v[k];
        float d = dot4(a, rv);
        if ((i & 3) == 0) a0 += d;
        else if ((i & 3) == 1) a1 += d;
        else if ((i & 3) == 2) a2 += d;
        else a3 += d;
    }
    float acc = (a0 + a1) + (a2 + a3);

    // Side dots split across disjoint thread ranges (640 elems total)
    if (t < 64) {                               // W_epsr row: 256 f = 64 float4
        float4 a = __ldcs(((const float4*)(W_epsr + (size_t)row * NZ)) + t);
        float4 e = ((const float4*)eps)[t];
        acc += dot4(a, e);
    } else if (t < 128) {                       // W_zr row · z (sum of split partials)
        const int k = t - 64;
        float4 a  = __ldcs(((const float4*)(W_zr + (size_t)row * NZ)) + k);
        float4 q0 = ((const float4*)g_zpart[0])[k];
        float4 q1 = ((const float4*)g_zpart[1])[k];
        float4 q2 = ((const float4*)g_zpart[2])[k];
        float4 q3 = ((const float4*)g_zpart[3])[k];
        float4 zz = make_float4(q0.x + q1.x + q2.x + q3.x,
                                q0.y + q1.y + q2.y + q3.y,
                                q0.z + q1.z + q2.z + q3.z,
                                q0.w + q1.w + q2.w + q3.w);
        acc += dot4(a, zz);
    } else if (t < 160) {                       // W_cr row: 128 f = 32 float4
        const int k = t - 128;
        float4 a  = __ldcs(((const float4*)(W_cr + (size_t)row * NC)) + k);
        float4 cc = ((const float4*)c)[k];
        acc += dot4(a, cc);
    }

    acc = block_reduce(acc);
    if (t == 0) {
        float xv = x[row];
        float xn = xv + DT_ * (acc - xv);
        out[row] = xn;
        float rn = tanhf(xn + b[row]);
        out[N + row] = rn;
        g_rn[row] = rn;
    }
}

// Kernel 3: split-K partials for z_new (rows 0..255 of W_rz) and c_new
// (rows 0..127 of W_rc) against r_new, with last-block finalize fused.
// Grid: (NZ+NC) * SPLITS blocks, 256 threads.
// Finalize sums partials in FIXED split order (bitwise-deterministic
// regardless of which split finishes last); counter reset for graph replay.
__global__ void __launch_bounds__(256) k_tail(
    const float* __restrict__ W_rz, const float* __restrict__ W_rc,
    const float* __restrict__ z_tilde, float* __restrict__ out)
{
    const int s   = blockIdx.x & (SPLITS - 1);
    const int idx = blockIdx.x >> 2;
    const float* __restrict__ Wrow = (idx < NZ)
        ? (W_rz + (size_t)idx * N)
        : (W_rc + (size_t)(idx - NZ) * N);
    const float4* __restrict__ w = (const float4*)Wrow;
    const float4* __restrict__ v = (const float4*)g_rn;
    const int c4 = s * CHUNK4 + threadIdx.x * 2;

    float acc = dot4(__ldcs(&w[c4]), v[c4]) + dot4(__ldcs(&w[c4 + 1]), v[c4 + 1]);
    acc = block_reduce(acc);
    if (threadIdx.x == 0) {
        g_tpart[s][idx] = acc;
        __threadfence();
        int old = atomicAdd(&g_cnt[idx], 1);
        if (old == SPLITS - 1) {
            // last split for this row: all partials globally visible
            float vsum = __ldcg(&g_tpart[0][idx]) + __ldcg(&g_tpart[1][idx])
                       + __ldcg(&g_tpart[2][idx]) + __ldcg(&g_tpart[3][idx]);
            if (idx < NZ) {
                out[2 * N + idx] = vsum;                           // z_new
                out[2 * N + NZ + NC + idx] = vsum - z_tilde[idx];  // eps_new
            } else {
                out[2 * N + NZ + (idx - NZ)] = vsum;               // c_new
            }
            g_cnt[idx] = 0;   // reset for next graph replay
        }
    }
}

extern "C" void kernel_launch(void* const* d_in, const int* in_sizes, int n_in,
                              void* d_out, int out_size) {
    // metadata order: x, eps, c, z_tilde, W_rr, W_zr, W_cr, W_epsr, W_rz, W_rc, b
    const float* x       = (const float*)d_in[0];
    const float* eps     = (const float*)d_in[1];
    const float* c       = (const float*)d_in[2];
    const float* z_tilde = (const float*)d_in[3];
    const float* W_rr    = (const float*)d_in[4];
    const float* W_zr    = (const float*)d_in[5];
    const float* W_cr    = (const float*)d_in[6];
    const float* W_epsr  = (const float*)d_in[7];
    const float* W_rz    = (const float*)d_in[8];
    const float* W_rc    = (const float*)d_in[9];
    const float* b       = (const float*)d_in[10];
    float* out = (float*)d_out;

    k_rz  <<<(NZ / ROWS_Z) * SPLITS, 256>>>(x, b, W_rz);
    k_big <<<N, 256>>>(W_rr, W_zr, W_cr, W_epsr, x, eps, c, b, out);
    k_tail<<<(NZ + NC) * SPLITS, 256>>>(W_rz, W_rc, z_tilde, out);
}